// round 4
// baseline (speedup 1.0000x reference)
#include <cuda_runtime.h>
#include <cstdint>

#define B_    4096
#define D_    1024
#define M_    16384
#define KTOT  131072
#define MK    64
#define AUXK  64
#define ROWCAP 1024
#define TIECAP 2048
#define NTOT  (B_ * M_)   /* 67108864 */

// ---------------- scratch (device globals; no allocation allowed) ----------------
static __device__ float g_pre[(size_t)B_ * M_];      // 256 MB pre-activations
static __device__ float g_dwT[(size_t)M_ * D_];      // 64 MB dec_w transposed [M, D]
static __device__ int   g_row_cnt[B_];
static __device__ int   g_row_cols[(size_t)B_ * ROWCAP];
static __device__ float g_row_vals[(size_t)B_ * ROWCAP];
static __device__ int   g_mk_cols[(size_t)B_ * MK];
static __device__ float g_mk_vals[(size_t)B_ * MK];
static __device__ unsigned g_h1[2048];
static __device__ unsigned g_h2[2048];
static __device__ unsigned g_h3[1024];
static __device__ unsigned g_selst[4];   // b1, r1, b2, r2
static __device__ unsigned g_cutoff_key;
static __device__ unsigned g_tie_need;
static __device__ int g_tie_cnt;
static __device__ int g_tie_idx[TIECAP];
static __device__ unsigned char g_active[M_];
static __device__ unsigned char g_deadmask[M_];
static __device__ int g_dead_cnt;
static __device__ int g_dead_list[M_];

// ---------------- init: reset all per-call state (graph replays!) ----------------
__global__ void k_init() {
    int i = blockIdx.x * blockDim.x + threadIdx.x;
    int n = blockDim.x * gridDim.x;
    for (int t = i; t < M_; t += n) g_active[t] = 0;
    for (int t = i; t < B_; t += n) g_row_cnt[t] = 0;
    for (int t = i; t < 2048; t += n) { g_h1[t] = 0; g_h2[t] = 0; }
    for (int t = i; t < 1024; t += n) g_h3[t] = 0;
    if (i == 0) { g_tie_cnt = 0; g_dead_cnt = 0; }
}

// ---------------- transpose dec_w [D, M] -> g_dwT [M, D] ----------------
__global__ void k_transpose(const float* __restrict__ dw) {
    __shared__ float t[32][33];
    int mb = blockIdx.x * 32, db = blockIdx.y * 32;
    int tx = threadIdx.x, ty = threadIdx.y;   // 32 x 8
#pragma unroll
    for (int i = 0; i < 32; i += 8)
        t[ty + i][tx] = dw[(size_t)(db + ty + i) * M_ + mb + tx];
    __syncthreads();
#pragma unroll
    for (int i = 0; i < 32; i += 8)
        g_dwT[(size_t)(mb + ty + i) * D_ + db + tx] = t[tx][ty + i];
}

// ---------------- fp32 SIMT GEMM: pre = (x - ib) @ enc_w^T + nb ----------------
__global__ __launch_bounds__(256, 2) void k_gemm(const float* __restrict__ X,
                                                 const float* __restrict__ W,
                                                 const float* __restrict__ ib,
                                                 const float* __restrict__ nb) {
    __shared__ float As[16][128];
    __shared__ float Bs[16][128];
    int tid = threadIdx.x;
    int n0 = blockIdx.x * 128;
    int m0 = blockIdx.y * 128;
    int tx = tid & 15, ty = tid >> 4;
    int lrow = tid >> 1;
    int lq = (tid & 1) << 1;   // 0 or 2

    float acc[8][8];
#pragma unroll
    for (int i = 0; i < 8; i++)
#pragma unroll
        for (int j = 0; j < 8; j++) acc[i][j] = 0.f;

    for (int k0 = 0; k0 < D_; k0 += 16) {
#pragma unroll
        for (int q = 0; q < 2; q++) {
            int c4 = lq + q;
            float4 av = *(const float4*)(X + (size_t)(m0 + lrow) * D_ + k0 + c4 * 4);
            float4 iv = *(const float4*)(ib + k0 + c4 * 4);
            As[c4 * 4 + 0][lrow] = av.x - iv.x;
            As[c4 * 4 + 1][lrow] = av.y - iv.y;
            As[c4 * 4 + 2][lrow] = av.z - iv.z;
            As[c4 * 4 + 3][lrow] = av.w - iv.w;
            float4 bv = *(const float4*)(W + (size_t)(n0 + lrow) * D_ + k0 + c4 * 4);
            Bs[c4 * 4 + 0][lrow] = bv.x;
            Bs[c4 * 4 + 1][lrow] = bv.y;
            Bs[c4 * 4 + 2][lrow] = bv.z;
            Bs[c4 * 4 + 3][lrow] = bv.w;
        }
        __syncthreads();
#pragma unroll
        for (int kk = 0; kk < 16; kk++) {
            float a[8], b[8];
            const float4* Ar = (const float4*)As[kk];
            const float4* Br = (const float4*)Bs[kk];
            float4 a0 = Ar[ty * 2], a1 = Ar[ty * 2 + 1];
            float4 b0 = Br[tx * 2], b1 = Br[tx * 2 + 1];
            a[0]=a0.x; a[1]=a0.y; a[2]=a0.z; a[3]=a0.w;
            a[4]=a1.x; a[5]=a1.y; a[6]=a1.z; a[7]=a1.w;
            b[0]=b0.x; b[1]=b0.y; b[2]=b0.z; b[3]=b0.w;
            b[4]=b1.x; b[5]=b1.y; b[6]=b1.z; b[7]=b1.w;
#pragma unroll
            for (int i = 0; i < 8; i++)
#pragma unroll
                for (int j = 0; j < 8; j++)
                    acc[i][j] = fmaf(a[i], b[j], acc[i][j]);
        }
        __syncthreads();
    }

    int col0 = n0 + tx * 8;
    float4 n0v = *(const float4*)(nb + col0);
    float4 n1v = *(const float4*)(nb + col0 + 4);
#pragma unroll
    for (int i = 0; i < 8; i++) {
        int mrow = m0 + ty * 8 + i;
        float* dst = g_pre + (size_t)mrow * M_ + col0;
        float4 r0 = make_float4(acc[i][0] + n0v.x, acc[i][1] + n0v.y,
                                acc[i][2] + n0v.z, acc[i][3] + n0v.w);
        float4 r1 = make_float4(acc[i][4] + n1v.x, acc[i][5] + n1v.y,
                                acc[i][6] + n1v.z, acc[i][7] + n1v.w);
        *(float4*)dst = r0;
        *(float4*)(dst + 4) = r1;
    }
}

// ---------------- global radix select: keys = bits of relu(v) ----------------
__device__ __forceinline__ unsigned relu_key(float v) {
    return (v > 0.f) ? __float_as_uint(v) : 0u;
}

__global__ void k_hist1() {
    __shared__ unsigned sh[2048];
    for (int t = threadIdx.x; t < 2048; t += blockDim.x) sh[t] = 0;
    __syncthreads();
    int stride = gridDim.x * blockDim.x;
    const float4* p4 = (const float4*)g_pre;
    for (int i = blockIdx.x * blockDim.x + threadIdx.x; i < NTOT / 4; i += stride) {
        float4 v = p4[i];
        atomicAdd(&sh[relu_key(v.x) >> 21], 1u);
        atomicAdd(&sh[relu_key(v.y) >> 21], 1u);
        atomicAdd(&sh[relu_key(v.z) >> 21], 1u);
        atomicAdd(&sh[relu_key(v.w) >> 21], 1u);
    }
    __syncthreads();
    for (int t = threadIdx.x; t < 2048; t += blockDim.x)
        if (sh[t]) atomicAdd(&g_h1[t], sh[t]);
}

__global__ void k_scan1() {
    if (threadIdx.x == 0) {
        unsigned acc = 0;
        for (int d = 2047; d >= 0; d--) {
            unsigned c = g_h1[d];
            if (acc + c >= (unsigned)KTOT) { g_selst[0] = d; g_selst[1] = KTOT - acc; break; }
            acc += c;
        }
    }
}

__global__ void k_hist2() {
    __shared__ unsigned sh[2048];
    for (int t = threadIdx.x; t < 2048; t += blockDim.x) sh[t] = 0;
    __syncthreads();
    unsigned b1 = g_selst[0];
    int stride = gridDim.x * blockDim.x;
    const float4* p4 = (const float4*)g_pre;
    for (int i = blockIdx.x * blockDim.x + threadIdx.x; i < NTOT / 4; i += stride) {
        float4 v = p4[i];
        unsigned k;
        k = relu_key(v.x); if ((k >> 21) == b1) atomicAdd(&sh[(k >> 10) & 2047], 1u);
        k = relu_key(v.y); if ((k >> 21) == b1) atomicAdd(&sh[(k >> 10) & 2047], 1u);
        k = relu_key(v.z); if ((k >> 21) == b1) atomicAdd(&sh[(k >> 10) & 2047], 1u);
        k = relu_key(v.w); if ((k >> 21) == b1) atomicAdd(&sh[(k >> 10) & 2047], 1u);
    }
    __syncthreads();
    for (int t = threadIdx.x; t < 2048; t += blockDim.x)
        if (sh[t]) atomicAdd(&g_h2[t], sh[t]);
}

__global__ void k_scan2() {
    if (threadIdx.x == 0) {
        unsigned K = g_selst[1], acc = 0;
        for (int d = 2047; d >= 0; d--) {
            unsigned c = g_h2[d];
            if (acc + c >= K) { g_selst[2] = d; g_selst[3] = K - acc; break; }
            acc += c;
        }
    }
}

__global__ void k_hist3() {
    __shared__ unsigned sh[1024];
    for (int t = threadIdx.x; t < 1024; t += blockDim.x) sh[t] = 0;
    __syncthreads();
    unsigned pre = (g_selst[0] << 11) | g_selst[2];
    int stride = gridDim.x * blockDim.x;
    const float4* p4 = (const float4*)g_pre;
    for (int i = blockIdx.x * blockDim.x + threadIdx.x; i < NTOT / 4; i += stride) {
        float4 v = p4[i];
        unsigned k;
        k = relu_key(v.x); if ((k >> 10) == pre) atomicAdd(&sh[k & 1023], 1u);
        k = relu_key(v.y); if ((k >> 10) == pre) atomicAdd(&sh[k & 1023], 1u);
        k = relu_key(v.z); if ((k >> 10) == pre) atomicAdd(&sh[k & 1023], 1u);
        k = relu_key(v.w); if ((k >> 10) == pre) atomicAdd(&sh[k & 1023], 1u);
    }
    __syncthreads();
    for (int t = threadIdx.x; t < 1024; t += blockDim.x)
        if (sh[t]) atomicAdd(&g_h3[t], sh[t]);
}

__global__ void k_scan3() {
    if (threadIdx.x == 0) {
        unsigned K = g_selst[3], acc = 0;
        for (int d = 1023; d >= 0; d--) {
            unsigned c = g_h3[d];
            if (acc + c >= K) {
                g_cutoff_key = (g_selst[0] << 21) | (g_selst[2] << 10) | (unsigned)d;
                g_tie_need = K - acc;
                break;
            }
            acc += c;
        }
    }
}

// ---------------- selection pass: write activ, row lists, ties, active flags ----------------
__global__ void k_select(float* __restrict__ activ) {
    unsigned cut = g_cutoff_key;
    int stride = gridDim.x * blockDim.x;
    const float4* p4 = (const float4*)g_pre;
    float4* o4 = (float4*)activ;
    for (int i = blockIdx.x * blockDim.x + threadIdx.x; i < NTOT / 4; i += stride) {
        float4 v = p4[i];
        float o[4];
        const float* vp = &v.x;
#pragma unroll
        for (int c = 0; c < 4; c++) {
            float val = vp[c];
            unsigned k = relu_key(val);
            float ov = 0.f;
            if (k > cut) {
                ov = val;
                int fi = i * 4 + c;
                int b = fi >> 14, m = fi & (M_ - 1);
                int p = atomicAdd(&g_row_cnt[b], 1);
                if (p < ROWCAP) {
                    g_row_cols[(size_t)b * ROWCAP + p] = m;
                    g_row_vals[(size_t)b * ROWCAP + p] = val;
                }
                g_active[m] = 1;
            } else if (k == cut && k != 0u) {
                int t = atomicAdd(&g_tie_cnt, 1);
                if (t < TIECAP) g_tie_idx[t] = i * 4 + c;
            }
            o[c] = ov;
        }
        o4[i] = make_float4(o[0], o[1], o[2], o[3]);
    }
}

__global__ void k_ties(float* __restrict__ activ) {
    __shared__ int tl[TIECAP];
    int n = g_tie_cnt; if (n > TIECAP) n = TIECAP;
    for (int t = threadIdx.x; t < n; t += blockDim.x) tl[t] = g_tie_idx[t];
    __syncthreads();
    for (int ph = 0; ph < n; ph++) {
        for (int i = (ph & 1) + 2 * threadIdx.x; i + 1 < n; i += 2 * blockDim.x) {
            int a = tl[i], b = tl[i + 1];
            if (a > b) { tl[i] = b; tl[i + 1] = a; }
        }
        __syncthreads();
    }
    int need = (int)g_tie_need; if (need > n) need = n;
    float cv = __uint_as_float(g_cutoff_key);
    for (int t = threadIdx.x; t < need; t += blockDim.x) {
        int fi = tl[t];
        activ[fi] = cv;
        int b = fi >> 14, m = fi & (M_ - 1);
        int p = atomicAdd(&g_row_cnt[b], 1);
        if (p < ROWCAP) {
            g_row_cols[(size_t)b * ROWCAP + p] = m;
            g_row_vals[(size_t)b * ROWCAP + p] = cv;
        }
        g_active[m] = 1;
    }
}

// ---------------- dead neuron bookkeeping (int32/int64 layout sniff) ----------------
__global__ void k_dead(const int* __restrict__ steps32) {
    // detect int64 vs int32 layout: int64 little-endian -> odd 32-bit words all zero
    bool is64 = true;
    for (int j = 1; j < 64; j += 2)
        if (steps32[j] != 0) { is64 = false; break; }
    int i = blockIdx.x * blockDim.x + threadIdx.x;
    int n = blockDim.x * gridDim.x;
    for (int m = i; m < M_; m += n) {
        long long st = (long long)(is64 ? steps32[2 * m] : steps32[m]) + 1;
        bool dead = (!g_active[m]) && (st > 256);
        g_deadmask[m] = dead ? 1 : 0;
        if (dead) {
            int p = atomicAdd(&g_dead_cnt, 1);
            g_dead_list[p] = m;
        }
    }
}

__global__ void k_deadsort() {
    int n = g_dead_cnt; if (n > M_) n = M_;
    for (int ph = 0; ph < n; ph++) {
        for (int i = (ph & 1) + 2 * threadIdx.x; i + 1 < n; i += 2 * blockDim.x) {
            int a = g_dead_list[i], b = g_dead_list[i + 1];
            if (a > b) { g_dead_list[i] = b; g_dead_list[i + 1] = a; }
        }
        __syncthreads();
    }
}

// ---------------- per-row top-64 (multi-k), exact with index-asc tie-break ----------------
__device__ __forceinline__ unsigned ord_key(float v) {
    unsigned u = __float_as_uint(v);
    return (u & 0x80000000u) ? ~u : (u | 0x80000000u);
}

__global__ __launch_bounds__(256) void k_multik() {
    int row = blockIdx.x;
    const float* pr = g_pre + (size_t)row * M_;
    __shared__ unsigned sh[2048];
    __shared__ int sb1, sr1, sb2, snsel, sncand;
    __shared__ unsigned ckey[256];
    __shared__ int ccol[256];
    int tid = threadIdx.x;

    for (int t = tid; t < 2048; t += 256) sh[t] = 0;
    __syncthreads();
    for (int c = tid; c < M_; c += 256)
        atomicAdd(&sh[ord_key(pr[c]) >> 21], 1u);
    __syncthreads();
    if (tid == 0) {
        unsigned acc = 0;
        for (int d = 2047; d >= 0; d--) {
            unsigned c = sh[d];
            if (acc + c >= (unsigned)MK) { sb1 = d; sr1 = MK - acc; break; }
            acc += c;
        }
    }
    __syncthreads();
    int b1 = sb1, r1 = sr1;

    for (int t = tid; t < 2048; t += 256) sh[t] = 0;
    __syncthreads();
    for (int c = tid; c < M_; c += 256) {
        unsigned k = ord_key(pr[c]);
        if ((int)(k >> 21) == b1) atomicAdd(&sh[(k >> 10) & 2047], 1u);
    }
    __syncthreads();
    if (tid == 0) {
        unsigned acc = 0;
        for (int d = 2047; d >= 0; d--) {
            unsigned c = sh[d];
            if (acc + c >= (unsigned)r1) { sb2 = d; break; }
            acc += c;
        }
        snsel = 0; sncand = 0;
    }
    __syncthreads();
    int b2 = sb2;

    for (int c = tid; c < M_; c += 256) {
        float v = pr[c];
        unsigned k = ord_key(v);
        int d1 = k >> 21;
        bool sel = false, cand = false;
        if (d1 > b1) sel = true;
        else if (d1 == b1) {
            int d2 = (k >> 10) & 2047;
            if (d2 > b2) sel = true;
            else if (d2 == b2) cand = true;
        }
        if (sel) {
            int p = atomicAdd(&snsel, 1);
            g_mk_cols[(size_t)row * MK + p] = c;
            g_mk_vals[(size_t)row * MK + p] = fmaxf(v, 0.f);
        } else if (cand) {
            int p = atomicAdd(&sncand, 1);
            if (p < 256) { ckey[p] = k; ccol[p] = c; }
        }
    }
    __syncthreads();
    int nsel = snsel;
    int need = MK - nsel;
    int nc = sncand; if (nc > 256) nc = 256;
    for (int t = tid; t < nc; t += 256) {
        unsigned mk = ckey[t];
        int mc = ccol[t];
        int rank = 0;
        for (int j = 0; j < nc; j++) {
            unsigned ok = ckey[j];
            if (ok > mk || (ok == mk && ccol[j] < mc)) rank++;
        }
        if (rank < need) {
            g_mk_cols[(size_t)row * MK + nsel + rank] = mc;
            g_mk_vals[(size_t)row * MK + nsel + rank] = fmaxf(pr[mc], 0.f);
        }
    }
}

// ---------------- aux top-64 over dead columns, XLA total-order tie semantics ----------------
// dead_pre = pre * mask. Non-dead cols: pre*0.0 = +0.0 if pre>=+0, -0.0 if pre<0
// (IEEE sign XOR). XLA top_k comparator is a TOTAL order on float bits: -0.0 < +0.0.
// So zero-fill takes ascending indices of +0.0 entries FIRST, then -0.0 entries.
__global__ void k_aux(float* __restrict__ av_out, float* __restrict__ ai_out) {
    int row = blockIdx.x * blockDim.x + threadIdx.x;
    if (row >= B_) return;
    const float* pr = g_pre + (size_t)row * M_;
    float pv[AUXK];
    int pidx[AUXK];
    int np = 0;
    int nd = g_dead_cnt; if (nd > M_) nd = M_;
    for (int t = 0; t < nd; t++) {
        int m = g_dead_list[t];               // ascending
        float v = pr[m];
        if (v > 0.f) {
            if (np == AUXK && v <= pv[AUXK - 1]) continue;
            int ins = (np < AUXK) ? np : AUXK - 1;
            while (ins > 0 && pv[ins - 1] < v) {
                pv[ins] = pv[ins - 1];
                pidx[ins] = pidx[ins - 1];
                ins--;
            }
            pv[ins] = v; pidx[ins] = m;
            if (np < AUXK) np++;
        }
    }
    float* av = av_out + (size_t)row * AUXK;
    float* ai = ai_out + (size_t)row * AUXK;
    int s = 0;
    for (; s < np; s++) { av[s] = pv[s]; ai[s] = (float)pidx[s]; }
    // +0.0 entries, ascending index
    int j = 0;
    while (s < AUXK && j < M_) {
        unsigned bits = __float_as_uint(pr[j]);
        bool plus_zero;
        if (g_deadmask[j]) plus_zero = (bits == 0u);                 // dead: dead_pre = pre, must be exactly +0.0
        else               plus_zero = ((bits & 0x80000000u) == 0u); // non-dead: pre*0.0 = +0.0 iff sign bit clear
        if (plus_zero) { av[s] = 0.f; ai[s] = (float)j; s++; }
        j++;
    }
    // -0.0 entries, ascending index (fallback; effectively unreachable)
    j = 0;
    while (s < AUXK && j < M_) {
        unsigned bits = __float_as_uint(pr[j]);
        bool minus_zero;
        if (g_deadmask[j]) minus_zero = (bits == 0x80000000u);
        else               minus_zero = ((bits & 0x80000000u) != 0u);
        if (minus_zero) { av[s] = 0.f; ai[s] = (float)j; s++; }
        j++;
    }
    while (s < AUXK) { av[s] = 0.f; ai[s] = 0.f; s++; }
}

// ---------------- sparse reconstructions ----------------
__global__ void k_recon(float* __restrict__ out, const float* __restrict__ ib) {
    int row = blockIdx.x;
    int d0 = threadIdx.x * 4;
    float4 acc = *(const float4*)(ib + d0);
    int n = g_row_cnt[row]; if (n > ROWCAP) n = ROWCAP;
    const int* cols = g_row_cols + (size_t)row * ROWCAP;
    const float* vals = g_row_vals + (size_t)row * ROWCAP;
    for (int i = 0; i < n; i++) {
        int m = cols[i];
        float v = vals[i];
        float4 w = *(const float4*)(g_dwT + (size_t)m * D_ + d0);
        acc.x = fmaf(v, w.x, acc.x);
        acc.y = fmaf(v, w.y, acc.y);
        acc.z = fmaf(v, w.z, acc.z);
        acc.w = fmaf(v, w.w, acc.w);
    }
    *(float4*)(out + (size_t)row * D_ + d0) = acc;
}

__global__ void k_mkrecon(float* __restrict__ out, const float* __restrict__ ib) {
    int row = blockIdx.x;
    int d0 = threadIdx.x * 4;
    float4 acc = *(const float4*)(ib + d0);
    const int* cols = g_mk_cols + (size_t)row * MK;
    const float* vals = g_mk_vals + (size_t)row * MK;
#pragma unroll 4
    for (int i = 0; i < MK; i++) {
        int m = cols[i];
        float v = vals[i];
        float4 w = *(const float4*)(g_dwT + (size_t)m * D_ + d0);
        acc.x = fmaf(v, w.x, acc.x);
        acc.y = fmaf(v, w.y, acc.y);
        acc.z = fmaf(v, w.z, acc.z);
        acc.w = fmaf(v, w.w, acc.w);
    }
    *(float4*)(out + (size_t)row * D_ + d0) = acc;
}

// ---------------- launch ----------------
extern "C" void kernel_launch(void* const* d_in, const int* in_sizes, int n_in,
                              void* d_out, int out_size) {
    const float* x     = (const float*)d_in[0];
    const float* enc_w = (const float*)d_in[1];
    const float* dec_w = (const float*)d_in[2];
    const float* ib    = (const float*)d_in[3];
    const float* nb    = (const float*)d_in[4];
    const int*   steps = (const int*)d_in[5];   // layout sniffed on device

    float* out = (float*)d_out;
    float* o_recon   = out;
    float* o_activ   = o_recon + (size_t)B_ * D_;
    float* o_mkrecon = o_activ + (size_t)B_ * M_;
    float* o_auxv    = o_mkrecon + (size_t)B_ * D_;
    float* o_auxi    = o_auxv + (size_t)B_ * AUXK;

    k_init<<<64, 256>>>();
    k_transpose<<<dim3(M_ / 32, D_ / 32), dim3(32, 8)>>>(dec_w);
    k_gemm<<<dim3(M_ / 128, B_ / 128), 256>>>(x, enc_w, ib, nb);
    k_hist1<<<2048, 256>>>();
    k_scan1<<<1, 32>>>();
    k_hist2<<<2048, 256>>>();
    k_scan2<<<1, 32>>>();
    k_hist3<<<2048, 256>>>();
    k_scan3<<<1, 32>>>();
    k_select<<<2048, 256>>>(o_activ);
    k_ties<<<1, 256>>>(o_activ);
    k_dead<<<64, 256>>>(steps);
    k_deadsort<<<1, 256>>>();
    k_multik<<<B_, 256>>>();
    k_aux<<<(B_ + 127) / 128, 128>>>(o_auxv, o_auxi);
    k_recon<<<B_, 256>>>(o_recon, ib);
    k_mkrecon<<<B_, 256>>>(o_mkrecon, ib);
}

// round 5
// speedup vs baseline: 1.0486x; 1.0486x over previous
#include <cuda_runtime.h>
#include <cstdint>

#define B_    4096
#define D_    1024
#define M_    16384
#define KTOT  131072
#define MK    64
#define AUXK  64
#define ROWCAP 1024
#define TIECAP 2048
#define NTOT  (B_ * M_)   /* 67108864 */

// ---------------- scratch (device globals; no allocation allowed) ----------------
static __device__ float g_pre[(size_t)B_ * M_];      // 256 MB pre-activations
static __device__ float g_dwT[(size_t)M_ * D_];      // 64 MB dec_w transposed [M, D]
static __device__ float g_xc[(size_t)B_ * D_];       // 16 MB centered x
static __device__ int   g_row_cnt[B_];
static __device__ int   g_row_cols[(size_t)B_ * ROWCAP];
static __device__ float g_row_vals[(size_t)B_ * ROWCAP];
static __device__ int   g_mk_cols[(size_t)B_ * MK];
static __device__ float g_mk_vals[(size_t)B_ * MK];
static __device__ unsigned g_h1[2048];
static __device__ unsigned g_h2[2048];
static __device__ unsigned g_h3[1024];
static __device__ unsigned g_selst[4];   // b1, r1, b2, r2
static __device__ unsigned g_cutoff_key;
static __device__ unsigned g_tie_need;
static __device__ int g_tie_cnt;
static __device__ int g_tie_idx[TIECAP];
static __device__ unsigned char g_active[M_];
static __device__ unsigned char g_deadmask[M_];
static __device__ int g_dead_cnt;
static __device__ int g_dead_list[M_];

// ---------------- init: reset all per-call state (graph replays!) ----------------
__global__ void k_init() {
    int i = blockIdx.x * blockDim.x + threadIdx.x;
    int n = blockDim.x * gridDim.x;
    for (int t = i; t < M_; t += n) g_active[t] = 0;
    for (int t = i; t < B_; t += n) g_row_cnt[t] = 0;
    for (int t = i; t < 2048; t += n) { g_h1[t] = 0; g_h2[t] = 0; }
    for (int t = i; t < 1024; t += n) g_h3[t] = 0;
    if (i == 0) { g_tie_cnt = 0; g_dead_cnt = 0; }
}

// ---------------- center x once: g_xc = x - ib (bitwise same subtraction) ----------------
__global__ void k_center(const float* __restrict__ x, const float* __restrict__ ib) {
    int i = blockIdx.x * blockDim.x + threadIdx.x;
    int n = blockDim.x * gridDim.x;
    const float4* x4 = (const float4*)x;
    float4* o4 = (float4*)g_xc;
    for (int t = i; t < B_ * D_ / 4; t += n) {
        int d0 = (t * 4) & (D_ - 1);
        float4 xv = x4[t];
        float4 iv = *(const float4*)(ib + d0);
        o4[t] = make_float4(xv.x - iv.x, xv.y - iv.y, xv.z - iv.z, xv.w - iv.w);
    }
}

// ---------------- transpose dec_w [D, M] -> g_dwT [M, D] ----------------
__global__ void k_transpose(const float* __restrict__ dw) {
    __shared__ float t[32][33];
    int mb = blockIdx.x * 32, db = blockIdx.y * 32;
    int tx = threadIdx.x, ty = threadIdx.y;   // 32 x 8
#pragma unroll
    for (int i = 0; i < 32; i += 8)
        t[ty + i][tx] = dw[(size_t)(db + ty + i) * M_ + mb + tx];
    __syncthreads();
#pragma unroll
    for (int i = 0; i < 32; i += 8)
        g_dwT[(size_t)(mb + ty + i) * D_ + db + tx] = t[tx][ty + i];
}

// ---------------- global radix select key ----------------
__device__ __forceinline__ unsigned relu_key(float v) {
    return (v > 0.f) ? __float_as_uint(v) : 0u;
}

// ---------------- fp32 SIMT GEMM: pre = g_xc @ enc_w^T + nb, fused hist1 ----------------
// Double-buffered smem, LDG prefetch overlapped with compute, 1 sync/tile.
// Per-output accumulation chain is IDENTICAL to the reference (ascending k FFMA).
__global__ __launch_bounds__(256, 2) void k_gemm(const float* __restrict__ W,
                                                 const float* __restrict__ nb) {
    __shared__ float As[2][16][128];
    __shared__ float Bs[2][16][128];
    __shared__ unsigned sh_h[2048];

    int tid = threadIdx.x;
    for (int t = tid; t < 2048; t += 256) sh_h[t] = 0;

    int n0 = blockIdx.x * 128;
    int m0 = blockIdx.y * 128;
    int tx = tid & 15, ty = tid >> 4;
    int lrow = tid >> 1;
    int lk = (tid & 1) * 8;      // k offset within tile: 0 or 8

    const float* xptr = g_xc + (size_t)(m0 + lrow) * D_ + lk;
    const float* wptr = W + (size_t)(n0 + lrow) * D_ + lk;

    float acc[8][8];
#pragma unroll
    for (int i = 0; i < 8; i++)
#pragma unroll
        for (int j = 0; j < 8; j++) acc[i][j] = 0.f;

    // prologue: tile 0 -> regs -> smem
    float4 xa0 = *(const float4*)(xptr);
    float4 xa1 = *(const float4*)(xptr + 4);
    float4 wb0 = *(const float4*)(wptr);
    float4 wb1 = *(const float4*)(wptr + 4);

    int buf = 0;
    {
        float* a = &As[buf][lk][lrow];
        a[0*128] = xa0.x; a[1*128] = xa0.y; a[2*128] = xa0.z; a[3*128] = xa0.w;
        a[4*128] = xa1.x; a[5*128] = xa1.y; a[6*128] = xa1.z; a[7*128] = xa1.w;
        float* b = &Bs[buf][lk][lrow];
        b[0*128] = wb0.x; b[1*128] = wb0.y; b[2*128] = wb0.z; b[3*128] = wb0.w;
        b[4*128] = wb1.x; b[5*128] = wb1.y; b[6*128] = wb1.z; b[7*128] = wb1.w;
    }
    __syncthreads();

#pragma unroll 1
    for (int t = 0; t < 64; t++) {
        // prefetch next tile into regs (overlaps with compute below)
        if (t < 63) {
            const float* xp = xptr + (t + 1) * 16;
            const float* wp = wptr + (t + 1) * 16;
            xa0 = *(const float4*)(xp);
            xa1 = *(const float4*)(xp + 4);
            wb0 = *(const float4*)(wp);
            wb1 = *(const float4*)(wp + 4);
        }
        // compute current tile from smem
#pragma unroll
        for (int kk = 0; kk < 16; kk++) {
            float a[8], b[8];
            const float4* Ar = (const float4*)As[buf][kk];
            const float4* Br = (const float4*)Bs[buf][kk];
            float4 a0 = Ar[ty * 2], a1 = Ar[ty * 2 + 1];
            float4 b0 = Br[tx * 2], b1 = Br[tx * 2 + 1];
            a[0]=a0.x; a[1]=a0.y; a[2]=a0.z; a[3]=a0.w;
            a[4]=a1.x; a[5]=a1.y; a[6]=a1.z; a[7]=a1.w;
            b[0]=b0.x; b[1]=b0.y; b[2]=b0.z; b[3]=b0.w;
            b[4]=b1.x; b[5]=b1.y; b[6]=b1.z; b[7]=b1.w;
#pragma unroll
            for (int i = 0; i < 8; i++)
#pragma unroll
                for (int j = 0; j < 8; j++)
                    acc[i][j] = fmaf(a[i], b[j], acc[i][j]);
        }
        if (t < 63) {
            int nb_ = buf ^ 1;
            float* a = &As[nb_][lk][lrow];
            a[0*128] = xa0.x; a[1*128] = xa0.y; a[2*128] = xa0.z; a[3*128] = xa0.w;
            a[4*128] = xa1.x; a[5*128] = xa1.y; a[6*128] = xa1.z; a[7*128] = xa1.w;
            float* b = &Bs[nb_][lk][lrow];
            b[0*128] = wb0.x; b[1*128] = wb0.y; b[2*128] = wb0.z; b[3*128] = wb0.w;
            b[4*128] = wb1.x; b[5*128] = wb1.y; b[6*128] = wb1.z; b[7*128] = wb1.w;
            __syncthreads();
            buf = nb_;
        }
    }

    // epilogue: +nb, write g_pre, fused hist1 (shared bins -> sparse global merge)
    int col0 = n0 + tx * 8;
    float4 n0v = *(const float4*)(nb + col0);
    float4 n1v = *(const float4*)(nb + col0 + 4);
#pragma unroll
    for (int i = 0; i < 8; i++) {
        int mrow = m0 + ty * 8 + i;
        float* dst = g_pre + (size_t)mrow * M_ + col0;
        float4 r0 = make_float4(acc[i][0] + n0v.x, acc[i][1] + n0v.y,
                                acc[i][2] + n0v.z, acc[i][3] + n0v.w);
        float4 r1 = make_float4(acc[i][4] + n1v.x, acc[i][5] + n1v.y,
                                acc[i][6] + n1v.z, acc[i][7] + n1v.w);
        *(float4*)dst = r0;
        *(float4*)(dst + 4) = r1;
        atomicAdd(&sh_h[relu_key(r0.x) >> 21], 1u);
        atomicAdd(&sh_h[relu_key(r0.y) >> 21], 1u);
        atomicAdd(&sh_h[relu_key(r0.z) >> 21], 1u);
        atomicAdd(&sh_h[relu_key(r0.w) >> 21], 1u);
        atomicAdd(&sh_h[relu_key(r1.x) >> 21], 1u);
        atomicAdd(&sh_h[relu_key(r1.y) >> 21], 1u);
        atomicAdd(&sh_h[relu_key(r1.z) >> 21], 1u);
        atomicAdd(&sh_h[relu_key(r1.w) >> 21], 1u);
    }
    __syncthreads();
    for (int t = tid; t < 2048; t += 256)
        if (sh_h[t]) atomicAdd(&g_h1[t], sh_h[t]);
}

__global__ void k_scan1() {
    if (threadIdx.x == 0) {
        unsigned acc = 0;
        for (int d = 2047; d >= 0; d--) {
            unsigned c = g_h1[d];
            if (acc + c >= (unsigned)KTOT) { g_selst[0] = d; g_selst[1] = KTOT - acc; break; }
            acc += c;
        }
    }
}

__global__ void k_hist2() {
    __shared__ unsigned sh[2048];
    for (int t = threadIdx.x; t < 2048; t += blockDim.x) sh[t] = 0;
    __syncthreads();
    unsigned b1 = g_selst[0];
    int stride = gridDim.x * blockDim.x;
    const float4* p4 = (const float4*)g_pre;
    for (int i = blockIdx.x * blockDim.x + threadIdx.x; i < NTOT / 4; i += stride) {
        float4 v = p4[i];
        unsigned k;
        k = relu_key(v.x); if ((k >> 21) == b1) atomicAdd(&sh[(k >> 10) & 2047], 1u);
        k = relu_key(v.y); if ((k >> 21) == b1) atomicAdd(&sh[(k >> 10) & 2047], 1u);
        k = relu_key(v.z); if ((k >> 21) == b1) atomicAdd(&sh[(k >> 10) & 2047], 1u);
        k = relu_key(v.w); if ((k >> 21) == b1) atomicAdd(&sh[(k >> 10) & 2047], 1u);
    }
    __syncthreads();
    for (int t = threadIdx.x; t < 2048; t += blockDim.x)
        if (sh[t]) atomicAdd(&g_h2[t], sh[t]);
}

__global__ void k_scan2() {
    if (threadIdx.x == 0) {
        unsigned K = g_selst[1], acc = 0;
        for (int d = 2047; d >= 0; d--) {
            unsigned c = g_h2[d];
            if (acc + c >= K) { g_selst[2] = d; g_selst[3] = K - acc; break; }
            acc += c;
        }
    }
}

__global__ void k_hist3() {
    __shared__ unsigned sh[1024];
    for (int t = threadIdx.x; t < 1024; t += blockDim.x) sh[t] = 0;
    __syncthreads();
    unsigned pre = (g_selst[0] << 11) | g_selst[2];
    int stride = gridDim.x * blockDim.x;
    const float4* p4 = (const float4*)g_pre;
    for (int i = blockIdx.x * blockDim.x + threadIdx.x; i < NTOT / 4; i += stride) {
        float4 v = p4[i];
        unsigned k;
        k = relu_key(v.x); if ((k >> 10) == pre) atomicAdd(&sh[k & 1023], 1u);
        k = relu_key(v.y); if ((k >> 10) == pre) atomicAdd(&sh[k & 1023], 1u);
        k = relu_key(v.z); if ((k >> 10) == pre) atomicAdd(&sh[k & 1023], 1u);
        k = relu_key(v.w); if ((k >> 10) == pre) atomicAdd(&sh[k & 1023], 1u);
    }
    __syncthreads();
    for (int t = threadIdx.x; t < 1024; t += blockDim.x)
        if (sh[t]) atomicAdd(&g_h3[t], sh[t]);
}

__global__ void k_scan3() {
    if (threadIdx.x == 0) {
        unsigned K = g_selst[3], acc = 0;
        for (int d = 1023; d >= 0; d--) {
            unsigned c = g_h3[d];
            if (acc + c >= K) {
                g_cutoff_key = (g_selst[0] << 21) | (g_selst[2] << 10) | (unsigned)d;
                g_tie_need = K - acc;
                break;
            }
            acc += c;
        }
    }
}

// ---------------- selection pass: write activ, row lists, ties, active flags ----------------
__global__ void k_select(float* __restrict__ activ) {
    unsigned cut = g_cutoff_key;
    int stride = gridDim.x * blockDim.x;
    const float4* p4 = (const float4*)g_pre;
    float4* o4 = (float4*)activ;
    for (int i = blockIdx.x * blockDim.x + threadIdx.x; i < NTOT / 4; i += stride) {
        float4 v = p4[i];
        float o[4];
        const float* vp = &v.x;
#pragma unroll
        for (int c = 0; c < 4; c++) {
            float val = vp[c];
            unsigned k = relu_key(val);
            float ov = 0.f;
            if (k > cut) {
                ov = val;
                int fi = i * 4 + c;
                int b = fi >> 14, m = fi & (M_ - 1);
                int p = atomicAdd(&g_row_cnt[b], 1);
                if (p < ROWCAP) {
                    g_row_cols[(size_t)b * ROWCAP + p] = m;
                    g_row_vals[(size_t)b * ROWCAP + p] = val;
                }
                g_active[m] = 1;
            } else if (k == cut && k != 0u) {
                int t = atomicAdd(&g_tie_cnt, 1);
                if (t < TIECAP) g_tie_idx[t] = i * 4 + c;
            }
            o[c] = ov;
        }
        o4[i] = make_float4(o[0], o[1], o[2], o[3]);
    }
}

__global__ void k_ties(float* __restrict__ activ) {
    __shared__ int tl[TIECAP];
    int n = g_tie_cnt; if (n > TIECAP) n = TIECAP;
    for (int t = threadIdx.x; t < n; t += blockDim.x) tl[t] = g_tie_idx[t];
    __syncthreads();
    for (int ph = 0; ph < n; ph++) {
        for (int i = (ph & 1) + 2 * threadIdx.x; i + 1 < n; i += 2 * blockDim.x) {
            int a = tl[i], b = tl[i + 1];
            if (a > b) { tl[i] = b; tl[i + 1] = a; }
        }
        __syncthreads();
    }
    int need = (int)g_tie_need; if (need > n) need = n;
    float cv = __uint_as_float(g_cutoff_key);
    for (int t = threadIdx.x; t < need; t += blockDim.x) {
        int fi = tl[t];
        activ[fi] = cv;
        int b = fi >> 14, m = fi & (M_ - 1);
        int p = atomicAdd(&g_row_cnt[b], 1);
        if (p < ROWCAP) {
            g_row_cols[(size_t)b * ROWCAP + p] = m;
            g_row_vals[(size_t)b * ROWCAP + p] = cv;
        }
        g_active[m] = 1;
    }
}

// ---------------- dead neuron bookkeeping (int32/int64 layout sniff) ----------------
__global__ void k_dead(const int* __restrict__ steps32) {
    bool is64 = true;
    for (int j = 1; j < 64; j += 2)
        if (steps32[j] != 0) { is64 = false; break; }
    int i = blockIdx.x * blockDim.x + threadIdx.x;
    int n = blockDim.x * gridDim.x;
    for (int m = i; m < M_; m += n) {
        long long st = (long long)(is64 ? steps32[2 * m] : steps32[m]) + 1;
        bool dead = (!g_active[m]) && (st > 256);
        g_deadmask[m] = dead ? 1 : 0;
        if (dead) {
            int p = atomicAdd(&g_dead_cnt, 1);
            g_dead_list[p] = m;
        }
    }
}

__global__ void k_deadsort() {
    int n = g_dead_cnt; if (n > M_) n = M_;
    for (int ph = 0; ph < n; ph++) {
        for (int i = (ph & 1) + 2 * threadIdx.x; i + 1 < n; i += 2 * blockDim.x) {
            int a = g_dead_list[i], b = g_dead_list[i + 1];
            if (a > b) { g_dead_list[i] = b; g_dead_list[i + 1] = a; }
        }
        __syncthreads();
    }
}

// ---------------- per-row top-64 (multi-k), exact with index-asc tie-break ----------------
__device__ __forceinline__ unsigned ord_key(float v) {
    unsigned u = __float_as_uint(v);
    return (u & 0x80000000u) ? ~u : (u | 0x80000000u);
}

__global__ __launch_bounds__(256) void k_multik() {
    int row = blockIdx.x;
    const float* pr = g_pre + (size_t)row * M_;
    __shared__ unsigned sh[2048];
    __shared__ int sb1, sr1, sb2, snsel, sncand;
    __shared__ unsigned ckey[256];
    __shared__ int ccol[256];
    int tid = threadIdx.x;

    for (int t = tid; t < 2048; t += 256) sh[t] = 0;
    __syncthreads();
    for (int c = tid; c < M_; c += 256)
        atomicAdd(&sh[ord_key(pr[c]) >> 21], 1u);
    __syncthreads();
    if (tid == 0) {
        unsigned acc = 0;
        for (int d = 2047; d >= 0; d--) {
            unsigned c = sh[d];
            if (acc + c >= (unsigned)MK) { sb1 = d; sr1 = MK - acc; break; }
            acc += c;
        }
    }
    __syncthreads();
    int b1 = sb1, r1 = sr1;

    for (int t = tid; t < 2048; t += 256) sh[t] = 0;
    __syncthreads();
    for (int c = tid; c < M_; c += 256) {
        unsigned k = ord_key(pr[c]);
        if ((int)(k >> 21) == b1) atomicAdd(&sh[(k >> 10) & 2047], 1u);
    }
    __syncthreads();
    if (tid == 0) {
        unsigned acc = 0;
        for (int d = 2047; d >= 0; d--) {
            unsigned c = sh[d];
            if (acc + c >= (unsigned)r1) { sb2 = d; break; }
            acc += c;
        }
        snsel = 0; sncand = 0;
    }
    __syncthreads();
    int b2 = sb2;

    for (int c = tid; c < M_; c += 256) {
        float v = pr[c];
        unsigned k = ord_key(v);
        int d1 = k >> 21;
        bool sel = false, cand = false;
        if (d1 > b1) sel = true;
        else if (d1 == b1) {
            int d2 = (k >> 10) & 2047;
            if (d2 > b2) sel = true;
            else if (d2 == b2) cand = true;
        }
        if (sel) {
            int p = atomicAdd(&snsel, 1);
            g_mk_cols[(size_t)row * MK + p] = c;
            g_mk_vals[(size_t)row * MK + p] = fmaxf(v, 0.f);
        } else if (cand) {
            int p = atomicAdd(&sncand, 1);
            if (p < 256) { ckey[p] = k; ccol[p] = c; }
        }
    }
    __syncthreads();
    int nsel = snsel;
    int need = MK - nsel;
    int nc = sncand; if (nc > 256) nc = 256;
    for (int t = tid; t < nc; t += 256) {
        unsigned mk = ckey[t];
        int mc = ccol[t];
        int rank = 0;
        for (int j = 0; j < nc; j++) {
            unsigned ok = ckey[j];
            if (ok > mk || (ok == mk && ccol[j] < mc)) rank++;
        }
        if (rank < need) {
            g_mk_cols[(size_t)row * MK + nsel + rank] = mc;
            g_mk_vals[(size_t)row * MK + nsel + rank] = fmaxf(pr[mc], 0.f);
        }
    }
}

// ---------------- aux top-64 over dead columns, XLA total-order tie semantics ----------------
__global__ void k_aux(float* __restrict__ av_out, float* __restrict__ ai_out) {
    int row = blockIdx.x * blockDim.x + threadIdx.x;
    if (row >= B_) return;
    const float* pr = g_pre + (size_t)row * M_;
    float pv[AUXK];
    int pidx[AUXK];
    int np = 0;
    int nd = g_dead_cnt; if (nd > M_) nd = M_;
    for (int t = 0; t < nd; t++) {
        int m = g_dead_list[t];               // ascending
        float v = pr[m];
        if (v > 0.f) {
            if (np == AUXK && v <= pv[AUXK - 1]) continue;
            int ins = (np < AUXK) ? np : AUXK - 1;
            while (ins > 0 && pv[ins - 1] < v) {
                pv[ins] = pv[ins - 1];
                pidx[ins] = pidx[ins - 1];
                ins--;
            }
            pv[ins] = v; pidx[ins] = m;
            if (np < AUXK) np++;
        }
    }
    float* av = av_out + (size_t)row * AUXK;
    float* ai = ai_out + (size_t)row * AUXK;
    int s = 0;
    for (; s < np; s++) { av[s] = pv[s]; ai[s] = (float)pidx[s]; }
    // +0.0 entries, ascending index
    int j = 0;
    while (s < AUXK && j < M_) {
        unsigned bits = __float_as_uint(pr[j]);
        bool plus_zero;
        if (g_deadmask[j]) plus_zero = (bits == 0u);
        else               plus_zero = ((bits & 0x80000000u) == 0u);
        if (plus_zero) { av[s] = 0.f; ai[s] = (float)j; s++; }
        j++;
    }
    // -0.0 entries, ascending index (fallback)
    j = 0;
    while (s < AUXK && j < M_) {
        unsigned bits = __float_as_uint(pr[j]);
        bool minus_zero;
        if (g_deadmask[j]) minus_zero = (bits == 0x80000000u);
        else               minus_zero = ((bits & 0x80000000u) != 0u);
        if (minus_zero) { av[s] = 0.f; ai[s] = (float)j; s++; }
        j++;
    }
    while (s < AUXK) { av[s] = 0.f; ai[s] = 0.f; s++; }
}

// ---------------- sparse reconstructions ----------------
__global__ void k_recon(float* __restrict__ out, const float* __restrict__ ib) {
    int row = blockIdx.x;
    int d0 = threadIdx.x * 4;
    float4 acc = *(const float4*)(ib + d0);
    int n = g_row_cnt[row]; if (n > ROWCAP) n = ROWCAP;
    const int* cols = g_row_cols + (size_t)row * ROWCAP;
    const float* vals = g_row_vals + (size_t)row * ROWCAP;
    for (int i = 0; i < n; i++) {
        int m = cols[i];
        float v = vals[i];
        float4 w = *(const float4*)(g_dwT + (size_t)m * D_ + d0);
        acc.x = fmaf(v, w.x, acc.x);
        acc.y = fmaf(v, w.y, acc.y);
        acc.z = fmaf(v, w.z, acc.z);
        acc.w = fmaf(v, w.w, acc.w);
    }
    *(float4*)(out + (size_t)row * D_ + d0) = acc;
}

__global__ void k_mkrecon(float* __restrict__ out, const float* __restrict__ ib) {
    int row = blockIdx.x;
    int d0 = threadIdx.x * 4;
    float4 acc = *(const float4*)(ib + d0);
    const int* cols = g_mk_cols + (size_t)row * MK;
    const float* vals = g_mk_vals + (size_t)row * MK;
#pragma unroll 4
    for (int i = 0; i < MK; i++) {
        int m = cols[i];
        float v = vals[i];
        float4 w = *(const float4*)(g_dwT + (size_t)m * D_ + d0);
        acc.x = fmaf(v, w.x, acc.x);
        acc.y = fmaf(v, w.y, acc.y);
        acc.z = fmaf(v, w.z, acc.z);
        acc.w = fmaf(v, w.w, acc.w);
    }
    *(float4*)(out + (size_t)row * D_ + d0) = acc;
}

// ---------------- launch ----------------
extern "C" void kernel_launch(void* const* d_in, const int* in_sizes, int n_in,
                              void* d_out, int out_size) {
    const float* x     = (const float*)d_in[0];
    const float* enc_w = (const float*)d_in[1];
    const float* dec_w = (const float*)d_in[2];
    const float* ib    = (const float*)d_in[3];
    const float* nb    = (const float*)d_in[4];
    const int*   steps = (const int*)d_in[5];   // layout sniffed on device

    float* out = (float*)d_out;
    float* o_recon   = out;
    float* o_activ   = o_recon + (size_t)B_ * D_;
    float* o_mkrecon = o_activ + (size_t)B_ * M_;
    float* o_auxv    = o_mkrecon + (size_t)B_ * D_;
    float* o_auxi    = o_auxv + (size_t)B_ * AUXK;

    k_init<<<64, 256>>>();
    k_center<<<256, 256>>>(x, ib);
    k_transpose<<<dim3(M_ / 32, D_ / 32), dim3(32, 8)>>>(dec_w);
    k_gemm<<<dim3(M_ / 128, B_ / 128), 256>>>(enc_w, nb);   // fused hist1
    k_scan1<<<1, 32>>>();
    k_hist2<<<2048, 256>>>();
    k_scan2<<<1, 32>>>();
    k_hist3<<<2048, 256>>>();
    k_scan3<<<1, 32>>>();
    k_select<<<2048, 256>>>(o_activ);
    k_ties<<<1, 256>>>(o_activ);
    k_dead<<<64, 256>>>(steps);
    k_deadsort<<<1, 256>>>();
    k_multik<<<B_, 256>>>();
    k_aux<<<(B_ + 127) / 128, 128>>>(o_auxv, o_auxi);
    k_recon<<<B_, 256>>>(o_recon, ib);
    k_mkrecon<<<B_, 256>>>(o_mkrecon, ib);
}